// round 7
// baseline (speedup 1.0000x reference)
#include <cuda_runtime.h>
#include <math.h>
#include <stdint.h>

#define MCOLS 65536
#define TCH   64
#define LRANK 8
#define NMF_ITERS 50
#define EPS_F 1.1920929e-07f
#define GRID  256                 // blocks in k_iterH / k_preconv / k_final
#define TILE  16384               // 64 rows * 256 cols per block tile
#define ITER_SMEM_BYTES 76032     // (16384 + 512 + 64 + 2048) floats * 4

// ---------------------------------------------------------------------------
// Scratch (no allocations allowed)
// ---------------------------------------------------------------------------
__device__ __align__(16) float g_Vt[GRID * TILE];      // tiled V: [bid][t][col]
__device__ __align__(16) float g_H[LRANK * MCOLS];
__device__ __align__(16) float g_W[TCH * LRANK];
__device__ __align__(16) float g_A[TCH * LRANK];
__device__ __align__(16) float g_partial[576 * GRID];  // [idx][block]
__device__ float g_red[256];
__device__ float g_red2[256];
__device__ float g_avg;
__device__ unsigned g_keys[4];

// ---------------------------------------------------------------------------
// Threefry-2x32 (JAX), 20 rounds
// ---------------------------------------------------------------------------
__device__ __forceinline__ void tf2x32(unsigned k0, unsigned k1,
                                       unsigned x0, unsigned x1,
                                       unsigned& o0, unsigned& o1) {
    unsigned ks2 = k0 ^ k1 ^ 0x1BD11BDAu;
    x0 += k0; x1 += k1;
#define TF_RND(r) { x0 += x1; x1 = (x1 << (r)) | (x1 >> (32 - (r))); x1 ^= x0; }
    TF_RND(13) TF_RND(15) TF_RND(26) TF_RND(6)
    x0 += k1;  x1 += ks2 + 1u;
    TF_RND(17) TF_RND(29) TF_RND(16) TF_RND(24)
    x0 += ks2; x1 += k0 + 2u;
    TF_RND(13) TF_RND(15) TF_RND(26) TF_RND(6)
    x0 += k0;  x1 += k1 + 3u;
    TF_RND(17) TF_RND(29) TF_RND(16) TF_RND(24)
    x0 += k1;  x1 += ks2 + 4u;
    TF_RND(13) TF_RND(15) TF_RND(26) TF_RND(6)
    x0 += ks2; x1 += k0 + 5u;
#undef TF_RND
    o0 = x0; o1 = x1;
}

__device__ __forceinline__ float bits_to_uniform(unsigned b) {
    return __uint_as_float((b >> 9) | 0x3f800000u) - 1.0f;
}

// ---------------------------------------------------------------------------
// K1: Vst = relu(w_pre @ eps + b_pre) -> tiled layout, + per-block sum
// grid 256 x 256; block bid owns columns [bid*256, bid*256+256)
// ---------------------------------------------------------------------------
__global__ __launch_bounds__(256) void k_preconv(const float* __restrict__ eps,
                                                 const float* __restrict__ wpre,
                                                 const float* __restrict__ bpre) {
    __shared__ __align__(16) float sT[4096];
    __shared__ float sb[64];
    __shared__ float ssum[256];
    int tid = threadIdx.x;
    for (int i = tid; i < 4096; i += 256) {
        int t = i >> 6, c = i & 63;
        sT[c * 64 + t] = wpre[i];
    }
    if (tid < 64) sb[tid] = bpre[tid];
    __syncthreads();

    int bid = blockIdx.x;
    int m = bid * 256 + tid;
    float acc[64];
#pragma unroll
    for (int t = 0; t < 64; t++) acc[t] = sb[t];
#pragma unroll 1
    for (int c = 0; c < 64; c++) {
        float e = eps[c * MCOLS + m];
        const float4* wr = (const float4*)&sT[c * 64];
#pragma unroll
        for (int q = 0; q < 16; q++) {
            float4 w = wr[q];
            acc[4 * q + 0] += w.x * e;
            acc[4 * q + 1] += w.y * e;
            acc[4 * q + 2] += w.z * e;
            acc[4 * q + 3] += w.w * e;
        }
    }
    float ls = 0.f;
    float* tile = g_Vt + bid * TILE;
#pragma unroll
    for (int t = 0; t < 64; t++) {
        float v = fmaxf(acc[t], 0.f);
        tile[t * 256 + tid] = v;
        ls += v;
    }
    ssum[tid] = ls; __syncthreads();
    for (int s = 128; s; s >>= 1) { if (tid < s) ssum[tid] += ssum[tid + s]; __syncthreads(); }
    if (tid == 0) g_red[blockIdx.x] = ssum[0];
}

// ---------------------------------------------------------------------------
// K2: avg + threefry keys (proven)
// ---------------------------------------------------------------------------
__global__ void k_scalar1() {
    __shared__ float s[256];
    int tid = threadIdx.x;
    s[tid] = g_red[tid];
    __syncthreads();
    for (int st = 128; st; st >>= 1) { if (tid < st) s[tid] += s[tid + st]; __syncthreads(); }
    if (tid == 0) {
        float mean = s[0] / (float)(TCH * MCOLS);
        g_avg = sqrtf(mean / (float)LRANK);
        unsigned o0, o1;
        tf2x32(0u, 0u, 0u, 0u, o0, o1); g_keys[0] = o0; g_keys[1] = o1;  // kW
        tf2x32(0u, 0u, 0u, 1u, o0, o1); g_keys[2] = o0; g_keys[3] = o1;  // kH
    }
}

// ---------------------------------------------------------------------------
// K3: W0, H0 init (proven)
// ---------------------------------------------------------------------------
__global__ void k_init() {
    unsigned i = blockIdx.x * 256u + threadIdx.x;   // < 524288
    float avg = g_avg;
    unsigned o0, o1;
    tf2x32(g_keys[2], g_keys[3], 0u, i, o0, o1);
    g_H[i] = avg * bits_to_uniform(o0 ^ o1);
    if (i < TCH * LRANK) {
        tf2x32(g_keys[0], g_keys[1], 0u, i, o0, o1);
        g_W[i] = avg * bits_to_uniform(o0 ^ o1);
    }
}

// ---------------------------------------------------------------------------
// K4: one NMF iteration, H-side + partial reductions; tiled V staged via float4.
//   grid MUST be GRID=256 blocks x 256 threads (1 col/thread).
//   Dynamic smem (floats): sV[0,16384) sW[16384,16896) sWtW[16896,16960)
//                          sHn[16960,19008)
// ---------------------------------------------------------------------------
__global__ __launch_bounds__(256, 2) void k_iterH() {
    extern __shared__ __align__(16) float sm[];
    float* sV   = sm;
    float* sW   = sm + 16384;
    float* sWtW = sm + 16896;
    float* sHn  = sm + 16960;

    int tid = threadIdx.x, lane = tid & 31, warp = tid >> 5;
    int bid = blockIdx.x;
    int m = bid * 256 + tid;

    // stage V tile: fully coalesced float4 copy of contiguous 64KB
    {
        const float4* t4 = (const float4*)(g_Vt + bid * TILE);
        float4* s4 = (float4*)sV;
#pragma unroll
        for (int i = 0; i < 16; i++) s4[i * 256 + tid] = t4[i * 256 + tid];
    }
    for (int i = tid; i < 512; i += 256) sW[i] = g_W[i];
    __syncthreads();

    if (tid < 64) {
        int l = tid >> 3, j = tid & 7;
        float s = 0.f;
#pragma unroll 8
        for (int t = 0; t < 64; t++) s += sW[t * 8 + l] * sW[t * 8 + j];
        sWtW[tid] = s;
    }
    __syncthreads();

    // --- phase 1: wtv = W^T v_col ; H update ---
    float h[8], wtv[8];
#pragma unroll
    for (int l = 0; l < 8; l++) { h[l] = g_H[l * MCOLS + m]; wtv[l] = 0.f; }
#pragma unroll 8
    for (int t = 0; t < 64; t++) {
        float v = sV[t * 256 + tid];
        const float4* w4 = (const float4*)&sW[t * 8];
        float4 wa = w4[0], wb = w4[1];
        wtv[0] += wa.x * v; wtv[1] += wa.y * v; wtv[2] += wa.z * v; wtv[3] += wa.w * v;
        wtv[4] += wb.x * v; wtv[5] += wb.y * v; wtv[6] += wb.z * v; wtv[7] += wb.w * v;
    }
#pragma unroll
    for (int l = 0; l < 8; l++) {
        const float4* q4 = (const float4*)&sWtW[l * 8];
        float4 qa = q4[0], qb = q4[1];
        float den = EPS_F
            + qa.x * h[0] + qa.y * h[1] + qa.z * h[2] + qa.w * h[3]
            + qb.x * h[4] + qb.y * h[5] + qb.z * h[6] + qb.w * h[7];
        float hn = h[l] * wtv[l] / den;
        g_H[l * MCOLS + m] = hn;
        sHn[l * 256 + tid] = hn;
    }
    __syncthreads();

    // --- phase 2: partial VHt (warp: 8 V-rows) + HHt (warp: its row) ---
    float acc[9][8];
#pragma unroll
    for (int a = 0; a < 9; a++)
#pragma unroll
        for (int l = 0; l < 8; l++) acc[a][l] = 0.f;

#pragma unroll 1
    for (int gg = 0; gg < 8; gg++) {
        int mm = gg * 32 + lane;
        float hl[8];
#pragma unroll
        for (int l = 0; l < 8; l++) hl[l] = sHn[l * 256 + mm];
#pragma unroll
        for (int tt = 0; tt < 8; tt++) {
            float v = sV[(warp * 8 + tt) * 256 + mm];
#pragma unroll
            for (int l = 0; l < 8; l++) acc[tt][l] += v * hl[l];
        }
        float hw = sHn[warp * 256 + mm];
#pragma unroll
        for (int l = 0; l < 8; l++) acc[8][l] += hw * hl[l];
    }

#pragma unroll
    for (int a = 0; a < 9; a++)
#pragma unroll
        for (int l = 0; l < 8; l++) {
            float x = acc[a][l];
#pragma unroll
            for (int s = 16; s; s >>= 1) x += __shfl_xor_sync(0xffffffffu, x, s);
            acc[a][l] = x;
        }
    if (lane == 0) {
#pragma unroll
        for (int tt = 0; tt < 8; tt++)
#pragma unroll
            for (int l = 0; l < 8; l++)
                g_partial[((warp * 8 + tt) * 8 + l) * GRID + bid] = acc[tt][l];
#pragma unroll
        for (int l = 0; l < 8; l++)
            g_partial[(512 + warp * 8 + l) * GRID + bid] = acc[8][l];
    }
}

// ---------------------------------------------------------------------------
// K5: reduce partials (256-wide) and update W. 1 block x 576 threads. (proven)
// ---------------------------------------------------------------------------
__global__ __launch_bounds__(576) void k_iterW() {
    __shared__ float sVHt[512];
    __shared__ float sHHt[64];
    int tid = threadIdx.x;
    float s = 0.f;
    {
        const float4* p = (const float4*)&g_partial[tid * GRID];
#pragma unroll 8
        for (int b = 0; b < GRID / 4; b++) { float4 v = p[b]; s += (v.x + v.y) + (v.z + v.w); }
    }
    if (tid < 512) sVHt[tid] = s; else sHHt[tid - 512] = s;
    __syncthreads();
    float wn = 0.f;
    if (tid < 512) {
        int t = tid >> 3, l = tid & 7;
        float den = EPS_F;
#pragma unroll
        for (int j = 0; j < 8; j++) den += g_W[t * 8 + j] * sHHt[j * 8 + l];
        wn = g_W[tid] * sVHt[tid] / den;
    }
    __syncthreads();
    if (tid < 512) g_W[tid] = wn;
}

// ---------------------------------------------------------------------------
// K6: A = w_post1 @ W
// ---------------------------------------------------------------------------
__global__ void k_postA(const float* __restrict__ wp1) {
    int tid = threadIdx.x;
    int t = tid >> 3, l = tid & 7;
    float s = 0.f;
#pragma unroll 8
    for (int c = 0; c < 64; c++) s += wp1[t * 64 + c] * g_W[c * 8 + l];
    g_A[tid] = s;
}

// ---------------------------------------------------------------------------
// K7: per column: vhat = W@h (error), y = relu(A@h), out = w_post2 @ y
// ---------------------------------------------------------------------------
__global__ __launch_bounds__(256) void k_final(const float* __restrict__ wp2,
                                               float* __restrict__ out) {
    __shared__ __align__(16) float sW[512];
    __shared__ __align__(16) float sA[512];
    __shared__ __align__(16) float sP[4096];
    __shared__ float ssum[256];
    int tid = threadIdx.x;
    for (int i = tid; i < 512; i += 256) { sW[i] = g_W[i]; sA[i] = g_A[i]; }
    for (int i = tid; i < 4096; i += 256) sP[i] = wp2[i];
    __syncthreads();

    int bid = blockIdx.x;
    int m = bid * 256 + tid;
    const float* tile = g_Vt + bid * TILE;
    float h[8];
#pragma unroll
    for (int l = 0; l < 8; l++) h[l] = g_H[l * MCOLS + m];

    float y[64];
    float err = 0.f;
#pragma unroll
    for (int t = 0; t < 64; t++) {
        const float4* w4 = (const float4*)&sW[t * 8];
        float4 wa = w4[0], wb = w4[1];
        float vh = wa.x * h[0] + wa.y * h[1] + wa.z * h[2] + wa.w * h[3]
                 + wb.x * h[4] + wb.y * h[5] + wb.z * h[6] + wb.w * h[7];
        const float4* a4 = (const float4*)&sA[t * 8];
        float4 aa = a4[0], ab = a4[1];
        float ya = aa.x * h[0] + aa.y * h[1] + aa.z * h[2] + aa.w * h[3]
                 + ab.x * h[4] + ab.y * h[5] + ab.z * h[6] + ab.w * h[7];
        float d = tile[t * 256 + tid] - vh;
        err += d * d;
        y[t] = fmaxf(ya, 0.f);
    }

#pragma unroll 1
    for (int t = 0; t < 64; t++) {
        const float4* p4 = (const float4*)&sP[t * 64];
        float o = 0.f;
#pragma unroll
        for (int q = 0; q < 16; q++) {
            float4 w = p4[q];
            o += w.x * y[4 * q] + w.y * y[4 * q + 1] + w.z * y[4 * q + 2] + w.w * y[4 * q + 3];
        }
        out[t * MCOLS + m] = o;
    }

    ssum[tid] = err; __syncthreads();
    for (int s = 128; s; s >>= 1) { if (tid < s) ssum[tid] += ssum[tid + s]; __syncthreads(); }
    if (tid == 0) g_red2[blockIdx.x] = ssum[0];
}

// ---------------------------------------------------------------------------
// K8: error
// ---------------------------------------------------------------------------
__global__ void k_err(float* __restrict__ out, int out_size) {
    __shared__ float s[256];
    int tid = threadIdx.x;
    s[tid] = g_red2[tid];
    __syncthreads();
    for (int st = 128; st; st >>= 1) { if (tid < st) s[tid] += s[tid + st]; __syncthreads(); }
    if (tid == 0) out[out_size - 1] = sqrtf(s[0]);
}

// ---------------------------------------------------------------------------
extern "C" void kernel_launch(void* const* d_in, const int* in_sizes, int n_in,
                              void* d_out, int out_size) {
    const float* eps  = (const float*)d_in[0];
    const float* wpre = (const float*)d_in[1];
    const float* bpre = (const float*)d_in[2];
    const float* wp1  = (const float*)d_in[3];
    const float* wp2  = (const float*)d_in[4];
    float* out = (float*)d_out;

    // One-time per-process attribute setup: uniform carveout across ALL
    // kernels so SMs never pay a shared-memory reconfiguration between the
    // 100 alternating launches in the graph.
    cudaFuncSetAttribute(k_iterH, cudaFuncAttributeMaxDynamicSharedMemorySize,
                         ITER_SMEM_BYTES);
    cudaFuncSetAttribute(k_preconv, cudaFuncAttributePreferredSharedMemoryCarveout, 100);
    cudaFuncSetAttribute(k_scalar1, cudaFuncAttributePreferredSharedMemoryCarveout, 100);
    cudaFuncSetAttribute(k_init,    cudaFuncAttributePreferredSharedMemoryCarveout, 100);
    cudaFuncSetAttribute(k_iterH,   cudaFuncAttributePreferredSharedMemoryCarveout, 100);
    cudaFuncSetAttribute(k_iterW,   cudaFuncAttributePreferredSharedMemoryCarveout, 100);
    cudaFuncSetAttribute(k_postA,   cudaFuncAttributePreferredSharedMemoryCarveout, 100);
    cudaFuncSetAttribute(k_final,   cudaFuncAttributePreferredSharedMemoryCarveout, 100);
    cudaFuncSetAttribute(k_err,     cudaFuncAttributePreferredSharedMemoryCarveout, 100);

    k_preconv<<<GRID, 256>>>(eps, wpre, bpre);
    k_scalar1<<<1, 256>>>();
    k_init<<<2048, 256>>>();
    for (int it = 0; it < NMF_ITERS; it++) {
        k_iterH<<<GRID, 256, ITER_SMEM_BYTES>>>();
        k_iterW<<<1, 576>>>();
    }
    k_postA<<<1, 512>>>(wp1);
    k_final<<<GRID, 256>>>(wp2, out);
    k_err<<<1, 256>>>(out, out_size);
}

// round 8
// speedup vs baseline: 1.2806x; 1.2806x over previous
#include <cuda_runtime.h>
#include <math.h>
#include <stdint.h>

#define MCOLS 65536
#define TCH   64
#define LRANK 8
#define NMF_ITERS 50
#define EPS_F 1.1920929e-07f
#define GRID  256                 // blocks in k_iterH; stride of g_partial

// ---------------------------------------------------------------------------
// Scratch (no allocations allowed)
// ---------------------------------------------------------------------------
__device__ __align__(16) float g_V[TCH * MCOLS];       // relu(conv), row-major
__device__ __align__(16) float g_H[LRANK * MCOLS];
__device__ __align__(16) float g_W[TCH * LRANK];
__device__ __align__(16) float g_partial[576 * GRID];  // [idx][block]
__device__ float g_red[256];
__device__ float g_red2[256];
__device__ float g_avg;
__device__ unsigned g_keys[4];

// ---------------------------------------------------------------------------
// Threefry-2x32 (JAX), 20 rounds
// ---------------------------------------------------------------------------
__device__ __forceinline__ void tf2x32(unsigned k0, unsigned k1,
                                       unsigned x0, unsigned x1,
                                       unsigned& o0, unsigned& o1) {
    unsigned ks2 = k0 ^ k1 ^ 0x1BD11BDAu;
    x0 += k0; x1 += k1;
#define TF_RND(r) { x0 += x1; x1 = (x1 << (r)) | (x1 >> (32 - (r))); x1 ^= x0; }
    TF_RND(13) TF_RND(15) TF_RND(26) TF_RND(6)
    x0 += k1;  x1 += ks2 + 1u;
    TF_RND(17) TF_RND(29) TF_RND(16) TF_RND(24)
    x0 += ks2; x1 += k0 + 2u;
    TF_RND(13) TF_RND(15) TF_RND(26) TF_RND(6)
    x0 += k0;  x1 += k1 + 3u;
    TF_RND(17) TF_RND(29) TF_RND(16) TF_RND(24)
    x0 += k1;  x1 += ks2 + 4u;
    TF_RND(13) TF_RND(15) TF_RND(26) TF_RND(6)
    x0 += ks2; x1 += k0 + 5u;
#undef TF_RND
    o0 = x0; o1 = x1;
}

__device__ __forceinline__ float bits_to_uniform(unsigned b) {
    return __uint_as_float((b >> 9) | 0x3f800000u) - 1.0f;
}

// ---------------------------------------------------------------------------
// K1: Vst = relu(w_pre @ eps + b_pre) + per-block sum   (R1-proven)
// ---------------------------------------------------------------------------
__global__ __launch_bounds__(256) void k_preconv(const float* __restrict__ eps,
                                                 const float* __restrict__ wpre,
                                                 const float* __restrict__ bpre) {
    __shared__ __align__(16) float sT[4096];
    __shared__ float sb[64];
    __shared__ float ssum[256];
    int tid = threadIdx.x;
    for (int i = tid; i < 4096; i += 256) {
        int t = i >> 6, c = i & 63;
        sT[c * 64 + t] = wpre[i];
    }
    if (tid < 64) sb[tid] = bpre[tid];
    __syncthreads();

    int m = blockIdx.x * 256 + tid;
    float acc[64];
#pragma unroll
    for (int t = 0; t < 64; t++) acc[t] = sb[t];
#pragma unroll 1
    for (int c = 0; c < 64; c++) {
        float e = eps[c * MCOLS + m];
        const float4* wr = (const float4*)&sT[c * 64];
#pragma unroll
        for (int q = 0; q < 16; q++) {
            float4 w = wr[q];
            acc[4 * q + 0] += w.x * e;
            acc[4 * q + 1] += w.y * e;
            acc[4 * q + 2] += w.z * e;
            acc[4 * q + 3] += w.w * e;
        }
    }
    float ls = 0.f;
#pragma unroll
    for (int t = 0; t < 64; t++) {
        float v = fmaxf(acc[t], 0.f);
        g_V[t * MCOLS + m] = v;
        ls += v;
    }
    ssum[tid] = ls; __syncthreads();
    for (int s = 128; s; s >>= 1) { if (tid < s) ssum[tid] += ssum[tid + s]; __syncthreads(); }
    if (tid == 0) g_red[blockIdx.x] = ssum[0];
}

// ---------------------------------------------------------------------------
// K2: avg + threefry keys (proven)
// ---------------------------------------------------------------------------
__global__ void k_scalar1() {
    __shared__ float s[256];
    int tid = threadIdx.x;
    s[tid] = g_red[tid];
    __syncthreads();
    for (int st = 128; st; st >>= 1) { if (tid < st) s[tid] += s[tid + st]; __syncthreads(); }
    if (tid == 0) {
        float mean = s[0] / (float)(TCH * MCOLS);
        g_avg = sqrtf(mean / (float)LRANK);
        unsigned o0, o1;
        tf2x32(0u, 0u, 0u, 0u, o0, o1); g_keys[0] = o0; g_keys[1] = o1;  // kW
        tf2x32(0u, 0u, 0u, 1u, o0, o1); g_keys[2] = o0; g_keys[3] = o1;  // kH
    }
}

// ---------------------------------------------------------------------------
// K3: W0, H0 init (proven)
// ---------------------------------------------------------------------------
__global__ void k_init() {
    unsigned i = blockIdx.x * 256u + threadIdx.x;   // < 524288
    float avg = g_avg;
    unsigned o0, o1;
    tf2x32(g_keys[2], g_keys[3], 0u, i, o0, o1);
    g_H[i] = avg * bits_to_uniform(o0 ^ o1);
    if (i < TCH * LRANK) {
        tf2x32(g_keys[0], g_keys[1], 0u, i, o0, o1);
        g_W[i] = avg * bits_to_uniform(o0 ^ o1);
    }
}

// ---------------------------------------------------------------------------
// K4: one NMF iteration, H-side + partial reductions. V direct from gmem/L2.
//   grid MUST be GRID=256 blocks x 256 threads (1 col/thread).
//   Static smem only (~10.5 KB) — no dynamic smem, no attribute calls.
// ---------------------------------------------------------------------------
__global__ __launch_bounds__(256, 2) void k_iterH() {
    __shared__ __align__(16) float sW[512];
    __shared__ __align__(16) float sWtW[64];
    __shared__ __align__(16) float sHn[8 * 256];

    int tid = threadIdx.x, lane = tid & 31, warp = tid >> 5;
    int bid = blockIdx.x;
    int m = bid * 256 + tid;

    for (int i = tid; i < 512; i += 256) sW[i] = g_W[i];
    __syncthreads();

    if (tid < 64) {
        int l = tid >> 3, j = tid & 7;
        float s = 0.f;
#pragma unroll 8
        for (int t = 0; t < 64; t++) s += sW[t * 8 + l] * sW[t * 8 + j];
        sWtW[tid] = s;
    }
    __syncthreads();

    // --- phase 1: wtv = W^T v_col ; H update ---
    float h[8], wtv[8];
#pragma unroll
    for (int l = 0; l < 8; l++) { h[l] = g_H[l * MCOLS + m]; wtv[l] = 0.f; }
#pragma unroll 8
    for (int t = 0; t < 64; t++) {
        float v = g_V[t * MCOLS + m];
        const float4* w4 = (const float4*)&sW[t * 8];
        float4 wa = w4[0], wb = w4[1];
        wtv[0] += wa.x * v; wtv[1] += wa.y * v; wtv[2] += wa.z * v; wtv[3] += wa.w * v;
        wtv[4] += wb.x * v; wtv[5] += wb.y * v; wtv[6] += wb.z * v; wtv[7] += wb.w * v;
    }
#pragma unroll
    for (int l = 0; l < 8; l++) {
        const float4* q4 = (const float4*)&sWtW[l * 8];
        float4 qa = q4[0], qb = q4[1];
        float den = EPS_F
            + qa.x * h[0] + qa.y * h[1] + qa.z * h[2] + qa.w * h[3]
            + qb.x * h[4] + qb.y * h[5] + qb.z * h[6] + qb.w * h[7];
        float hn = h[l] * wtv[l] / den;
        g_H[l * MCOLS + m] = hn;
        sHn[l * 256 + tid] = hn;
    }
    __syncthreads();

    // --- phase 2: partial VHt (warp: 8 V-rows) + HHt (warp: its row) ---
    float acc[9][8];
#pragma unroll
    for (int a = 0; a < 9; a++)
#pragma unroll
        for (int l = 0; l < 8; l++) acc[a][l] = 0.f;

#pragma unroll 1
    for (int gg = 0; gg < 8; gg++) {
        int mm = gg * 32 + lane;
        float hl[8];
#pragma unroll
        for (int l = 0; l < 8; l++) hl[l] = sHn[l * 256 + mm];
#pragma unroll
        for (int tt = 0; tt < 8; tt++) {
            float v = g_V[(warp * 8 + tt) * MCOLS + bid * 256 + mm];
#pragma unroll
            for (int l = 0; l < 8; l++) acc[tt][l] += v * hl[l];
        }
        float hw = sHn[warp * 256 + mm];
#pragma unroll
        for (int l = 0; l < 8; l++) acc[8][l] += hw * hl[l];
    }

#pragma unroll
    for (int a = 0; a < 9; a++)
#pragma unroll
        for (int l = 0; l < 8; l++) {
            float x = acc[a][l];
#pragma unroll
            for (int s = 16; s; s >>= 1) x += __shfl_xor_sync(0xffffffffu, x, s);
            acc[a][l] = x;
        }
    if (lane == 0) {
#pragma unroll
        for (int tt = 0; tt < 8; tt++)
#pragma unroll
            for (int l = 0; l < 8; l++)
                g_partial[((warp * 8 + tt) * 8 + l) * GRID + bid] = acc[tt][l];
#pragma unroll
        for (int l = 0; l < 8; l++)
            g_partial[(512 + warp * 8 + l) * GRID + bid] = acc[8][l];
    }
}

// ---------------------------------------------------------------------------
// K5: reduce partials (256-wide) and update W. 1 block x 576 threads. (proven)
// ---------------------------------------------------------------------------
__global__ __launch_bounds__(576) void k_iterW() {
    __shared__ float sVHt[512];
    __shared__ float sHHt[64];
    int tid = threadIdx.x;
    float s = 0.f;
    {
        const float4* p = (const float4*)&g_partial[tid * GRID];
#pragma unroll 8
        for (int b = 0; b < GRID / 4; b++) { float4 v = p[b]; s += (v.x + v.y) + (v.z + v.w); }
    }
    if (tid < 512) sVHt[tid] = s; else sHHt[tid - 512] = s;
    __syncthreads();
    float wn = 0.f;
    if (tid < 512) {
        int t = tid >> 3, l = tid & 7;
        float den = EPS_F;
#pragma unroll
        for (int j = 0; j < 8; j++) den += g_W[t * 8 + j] * sHHt[j * 8 + l];
        wn = g_W[tid] * sVHt[tid] / den;
    }
    __syncthreads();
    if (tid < 512) g_W[tid] = wn;
}

// ---------------------------------------------------------------------------
// K6: fused epilogue: A = w_post1@W (per-block, redundant), then per column:
//     vhat = W@h (error), y = relu(A@h), out = w_post2 @ y
// ---------------------------------------------------------------------------
__global__ __launch_bounds__(256) void k_final(const float* __restrict__ wp1,
                                               const float* __restrict__ wp2,
                                               float* __restrict__ out) {
    __shared__ __align__(16) float sW[512];
    __shared__ __align__(16) float sA[512];
    __shared__ __align__(16) float sP[4096];
    __shared__ float ssum[256];
    int tid = threadIdx.x;
    for (int i = tid; i < 512; i += 256) sW[i] = g_W[i];
    for (int i = tid; i < 4096; i += 256) sP[i] = wp2[i];
    __syncthreads();

    // A = w_post1 @ W: thread computes entries tid and tid+256
    {
        int t0 = tid >> 3, l0 = tid & 7;
        float s0 = 0.f;
#pragma unroll 8
        for (int c = 0; c < 64; c++) s0 += wp1[t0 * 64 + c] * sW[c * 8 + l0];
        sA[tid] = s0;
        int i1 = tid + 256;
        int t1 = i1 >> 3, l1 = i1 & 7;
        float s1 = 0.f;
#pragma unroll 8
        for (int c = 0; c < 64; c++) s1 += wp1[t1 * 64 + c] * sW[c * 8 + l1];
        sA[i1] = s1;
    }
    __syncthreads();

    int m = blockIdx.x * 256 + tid;
    float h[8];
#pragma unroll
    for (int l = 0; l < 8; l++) h[l] = g_H[l * MCOLS + m];

    float y[64];
    float err = 0.f;
#pragma unroll
    for (int t = 0; t < 64; t++) {
        const float4* w4 = (const float4*)&sW[t * 8];
        float4 wa = w4[0], wb = w4[1];
        float vh = wa.x * h[0] + wa.y * h[1] + wa.z * h[2] + wa.w * h[3]
                 + wb.x * h[4] + wb.y * h[5] + wb.z * h[6] + wb.w * h[7];
        const float4* a4 = (const float4*)&sA[t * 8];
        float4 aa = a4[0], ab = a4[1];
        float ya = aa.x * h[0] + aa.y * h[1] + aa.z * h[2] + aa.w * h[3]
                 + ab.x * h[4] + ab.y * h[5] + ab.z * h[6] + ab.w * h[7];
        float d = g_V[t * MCOLS + m] - vh;
        err += d * d;
        y[t] = fmaxf(ya, 0.f);
    }

#pragma unroll 1
    for (int t = 0; t < 64; t++) {
        const float4* p4 = (const float4*)&sP[t * 64];
        float o = 0.f;
#pragma unroll
        for (int q = 0; q < 16; q++) {
            float4 w = p4[q];
            o += w.x * y[4 * q] + w.y * y[4 * q + 1] + w.z * y[4 * q + 2] + w.w * y[4 * q + 3];
        }
        out[t * MCOLS + m] = o;
    }

    ssum[tid] = err; __syncthreads();
    for (int s = 128; s; s >>= 1) { if (tid < s) ssum[tid] += ssum[tid + s]; __syncthreads(); }
    if (tid == 0) g_red2[blockIdx.x] = ssum[0];
}

// ---------------------------------------------------------------------------
// K7: error
// ---------------------------------------------------------------------------
__global__ void k_err(float* __restrict__ out, int out_size) {
    __shared__ float s[256];
    int tid = threadIdx.x;
    s[tid] = g_red2[tid];
    __syncthreads();
    for (int st = 128; st; st >>= 1) { if (tid < st) s[tid] += s[tid + st]; __syncthreads(); }
    if (tid == 0) out[out_size - 1] = sqrtf(s[0]);
}

// ---------------------------------------------------------------------------
extern "C" void kernel_launch(void* const* d_in, const int* in_sizes, int n_in,
                              void* d_out, int out_size) {
    const float* eps  = (const float*)d_in[0];
    const float* wpre = (const float*)d_in[1];
    const float* bpre = (const float*)d_in[2];
    const float* wp1  = (const float*)d_in[3];
    const float* wp2  = (const float*)d_in[4];
    float* out = (float*)d_out;

    k_preconv<<<256, 256>>>(eps, wpre, bpre);
    k_scalar1<<<1, 256>>>();
    k_init<<<2048, 256>>>();
    for (int it = 0; it < NMF_ITERS; it++) {
        k_iterH<<<GRID, 256>>>();
        k_iterW<<<1, 576>>>();
    }
    k_final<<<256, 256>>>(wp1, wp2, out);
    k_err<<<1, 256>>>(out, out_size);
}

// round 9
// speedup vs baseline: 1.4856x; 1.1601x over previous
#include <cuda_runtime.h>
#include <math.h>
#include <stdint.h>

#define MCOLS 65536
#define TCH   64
#define LRANK 8
#define NMF_ITERS 50
#define EPS_F 1.1920929e-07f
#define GRID  128                 // blocks in k_iter; stride of partials

// ---------------------------------------------------------------------------
// Scratch (no allocations allowed)
// ---------------------------------------------------------------------------
__device__ __align__(16) float g_V[TCH * MCOLS];          // relu(conv), row-major
__device__ __align__(16) float g_H[LRANK * MCOLS];
__device__ __align__(16) float g_Wb[2][TCH * LRANK];      // W parity buffers
__device__ __align__(16) float g_Wfin[TCH * LRANK];       // W_50 for epilogue
__device__ __align__(16) float g_partialBuf[2][576 * GRID];  // [parity][idx][block]
__device__ float g_red[256];
__device__ float g_red2[256];

// ---------------------------------------------------------------------------
// Threefry-2x32 (JAX), 20 rounds
// ---------------------------------------------------------------------------
__device__ __forceinline__ void tf2x32(unsigned k0, unsigned k1,
                                       unsigned x0, unsigned x1,
                                       unsigned& o0, unsigned& o1) {
    unsigned ks2 = k0 ^ k1 ^ 0x1BD11BDAu;
    x0 += k0; x1 += k1;
#define TF_RND(r) { x0 += x1; x1 = (x1 << (r)) | (x1 >> (32 - (r))); x1 ^= x0; }
    TF_RND(13) TF_RND(15) TF_RND(26) TF_RND(6)
    x0 += k1;  x1 += ks2 + 1u;
    TF_RND(17) TF_RND(29) TF_RND(16) TF_RND(24)
    x0 += ks2; x1 += k0 + 2u;
    TF_RND(13) TF_RND(15) TF_RND(26) TF_RND(6)
    x0 += k0;  x1 += k1 + 3u;
    TF_RND(17) TF_RND(29) TF_RND(16) TF_RND(24)
    x0 += k1;  x1 += ks2 + 4u;
    TF_RND(13) TF_RND(15) TF_RND(26) TF_RND(6)
    x0 += ks2; x1 += k0 + 5u;
#undef TF_RND
    o0 = x0; o1 = x1;
}

__device__ __forceinline__ float bits_to_uniform(unsigned b) {
    return __uint_as_float((b >> 9) | 0x3f800000u) - 1.0f;
}

// ---------------------------------------------------------------------------
// K1: Vst = relu(w_pre @ eps + b_pre) + per-block sum   (proven)
// grid MUST be 256 x 256
// ---------------------------------------------------------------------------
__global__ __launch_bounds__(256) void k_preconv(const float* __restrict__ eps,
                                                 const float* __restrict__ wpre,
                                                 const float* __restrict__ bpre) {
    __shared__ __align__(16) float sT[4096];
    __shared__ float sb[64];
    __shared__ float ssum[256];
    int tid = threadIdx.x;
    for (int i = tid; i < 4096; i += 256) {
        int t = i >> 6, c = i & 63;
        sT[c * 64 + t] = wpre[i];
    }
    if (tid < 64) sb[tid] = bpre[tid];
    __syncthreads();

    int m = blockIdx.x * 256 + tid;
    float acc[64];
#pragma unroll
    for (int t = 0; t < 64; t++) acc[t] = sb[t];
#pragma unroll 1
    for (int c = 0; c < 64; c++) {
        float e = eps[c * MCOLS + m];
        const float4* wr = (const float4*)&sT[c * 64];
#pragma unroll
        for (int q = 0; q < 16; q++) {
            float4 w = wr[q];
            acc[4 * q + 0] += w.x * e;
            acc[4 * q + 1] += w.y * e;
            acc[4 * q + 2] += w.z * e;
            acc[4 * q + 3] += w.w * e;
        }
    }
    float ls = 0.f;
#pragma unroll
    for (int t = 0; t < 64; t++) {
        float v = fmaxf(acc[t], 0.f);
        g_V[t * MCOLS + m] = v;
        ls += v;
    }
    ssum[tid] = ls; __syncthreads();
    for (int s = 128; s; s >>= 1) { if (tid < s) ssum[tid] += ssum[tid + s]; __syncthreads(); }
    if (tid == 0) g_red[blockIdx.x] = ssum[0];
}

// ---------------------------------------------------------------------------
// K2: fused scalar+init. Each block redundantly computes avg (exact k_scalar1
//     tree order) + threefry keys, then its slice of H0 / W0 (exact k_init).
//     grid MUST be 2048 x 256. W0 -> g_Wb[0].
// ---------------------------------------------------------------------------
__global__ __launch_bounds__(256) void k_init() {
    __shared__ float s[256];
    __shared__ unsigned skeys[4];
    __shared__ float savg;
    int tid = threadIdx.x;
    s[tid] = g_red[tid];
    __syncthreads();
    for (int st = 128; st; st >>= 1) { if (tid < st) s[tid] += s[tid + st]; __syncthreads(); }
    if (tid == 0) {
        float mean = s[0] / (float)(TCH * MCOLS);
        savg = sqrtf(mean / (float)LRANK);
        unsigned o0, o1;
        tf2x32(0u, 0u, 0u, 0u, o0, o1); skeys[0] = o0; skeys[1] = o1;  // kW
        tf2x32(0u, 0u, 0u, 1u, o0, o1); skeys[2] = o0; skeys[3] = o1;  // kH
    }
    __syncthreads();

    unsigned i = blockIdx.x * 256u + tid;   // < 524288
    float avg = savg;
    unsigned o0, o1;
    tf2x32(skeys[2], skeys[3], 0u, i, o0, o1);
    g_H[i] = avg * bits_to_uniform(o0 ^ o1);
    if (i < TCH * LRANK) {
        tf2x32(skeys[0], skeys[1], 0u, i, o0, o1);
        g_Wb[0][i] = avg * bits_to_uniform(o0 ^ o1);
    }
}

// ---------------------------------------------------------------------------
// K3: one fused NMF iteration (launch k = iteration k):
//   prologue (k>0): each block redundantly reduces partials P_{k-1} and
//                   computes W_k = Wupd(W_{k-1}, P_{k-1})  [k_iterW order]
//                   block 0 publishes W_k to g_Wb[(k+1)&1]
//   then (exact R1 k_iterH): WtW, H update (H_k -> H_{k+1}),
//                   partials P_k -> g_partialBuf[k&1]
//   grid MUST be GRID=128 blocks x 256 threads (512 cols/block, 2 reps)
// ---------------------------------------------------------------------------
__global__ __launch_bounds__(256) void k_iter(int it) {
    __shared__ __align__(16) float sW[512];
    __shared__ __align__(16) float sWtW[64];
    __shared__ __align__(16) float sRed[576];
    __shared__ float sHn[8][256];
    int tid = threadIdx.x, lane = tid & 31, warp = tid >> 5;
    int bid = blockIdx.x;
    int m0 = bid * 512;

    const float* __restrict__ Wold = g_Wb[it & 1];
    float* __restrict__ pbufW = g_partialBuf[it & 1];

    if (it > 0) {
        const float* __restrict__ P = g_partialBuf[(it + 1) & 1];  // P_{it-1}
        // per-block redundant reduction, exact k_iterW order per output
        for (int o = tid; o < 576; o += 256) {
            const float4* p = (const float4*)&P[o * GRID];
            float s = 0.f;
#pragma unroll 8
            for (int b = 0; b < GRID / 4; b++) { float4 v = p[b]; s += (v.x + v.y) + (v.z + v.w); }
            sRed[o] = s;
        }
        __syncthreads();
        // W update, exact k_iterW math
        float nw0, nw1;
        {
            int i0 = tid;
            int t0 = i0 >> 3, l0 = i0 & 7;
            float den0 = EPS_F;
#pragma unroll
            for (int j = 0; j < 8; j++) den0 += Wold[t0 * 8 + j] * sRed[512 + j * 8 + l0];
            nw0 = Wold[i0] * sRed[i0] / den0;
            int i1 = tid + 256;
            int t1 = i1 >> 3, l1 = i1 & 7;
            float den1 = EPS_F;
#pragma unroll
            for (int j = 0; j < 8; j++) den1 += Wold[t1 * 8 + j] * sRed[512 + j * 8 + l1];
            nw1 = Wold[i1] * sRed[i1] / den1;
        }
        sW[tid] = nw0;
        sW[tid + 256] = nw1;
        if (bid == 0) {
            g_Wb[(it + 1) & 1][tid] = nw0;
            g_Wb[(it + 1) & 1][tid + 256] = nw1;
        }
    } else {
        sW[tid] = Wold[tid];
        sW[tid + 256] = Wold[tid + 256];
        if (bid == 0) {
            g_Wb[1][tid] = Wold[tid];
            g_Wb[1][tid + 256] = Wold[tid + 256];
        }
    }
    __syncthreads();

    // WtW (exact R1)
    if (tid < 64) {
        int l = tid >> 3, j = tid & 7;
        float s = 0.f;
#pragma unroll 8
        for (int t = 0; t < 64; t++) s += sW[t * 8 + l] * sW[t * 8 + j];
        sWtW[tid] = s;
    }
    __syncthreads();

    float acc[9][8];
#pragma unroll
    for (int a = 0; a < 9; a++)
#pragma unroll
        for (int l = 0; l < 8; l++) acc[a][l] = 0.f;

#pragma unroll 1
    for (int rep = 0; rep < 2; rep++) {
        int m = m0 + rep * 256 + tid;
        float h[8], wtv[8];
#pragma unroll
        for (int l = 0; l < 8; l++) { h[l] = g_H[l * MCOLS + m]; wtv[l] = 0.f; }
#pragma unroll 4
        for (int t = 0; t < 64; t++) {
            float v = g_V[t * MCOLS + m];
            const float4* w4 = (const float4*)&sW[t * 8];
            float4 wa = w4[0], wb = w4[1];
            wtv[0] += wa.x * v; wtv[1] += wa.y * v; wtv[2] += wa.z * v; wtv[3] += wa.w * v;
            wtv[4] += wb.x * v; wtv[5] += wb.y * v; wtv[6] += wb.z * v; wtv[7] += wb.w * v;
        }
#pragma unroll
        for (int l = 0; l < 8; l++) {
            const float4* q4 = (const float4*)&sWtW[l * 8];
            float4 qa = q4[0], qb = q4[1];
            float den = EPS_F
                + qa.x * h[0] + qa.y * h[1] + qa.z * h[2] + qa.w * h[3]
                + qb.x * h[4] + qb.y * h[5] + qb.z * h[6] + qb.w * h[7];
            float hn = h[l] * wtv[l] / den;
            g_H[l * MCOLS + m] = hn;
            sHn[l][tid] = hn;
        }
        __syncthreads();

        // phase 2: warp w handles V rows [8w, 8w+8) and Hn row w
#pragma unroll 1
        for (int gg = 0; gg < 8; gg++) {
            int mm = gg * 32 + lane;
            float hl[8];
#pragma unroll
            for (int l = 0; l < 8; l++) hl[l] = sHn[l][mm];
#pragma unroll
            for (int tt = 0; tt < 8; tt++) {
                float v = g_V[(warp * 8 + tt) * MCOLS + m0 + rep * 256 + mm];
#pragma unroll
                for (int l = 0; l < 8; l++) acc[tt][l] += v * hl[l];
            }
            float hw = sHn[warp][mm];
#pragma unroll
            for (int l = 0; l < 8; l++) acc[8][l] += hw * hl[l];
        }
        __syncthreads();
    }

    // deterministic lane reduction (butterfly), exact R1
#pragma unroll
    for (int a = 0; a < 9; a++)
#pragma unroll
        for (int l = 0; l < 8; l++) {
            float x = acc[a][l];
#pragma unroll
            for (int s = 16; s; s >>= 1) x += __shfl_xor_sync(0xffffffffu, x, s);
            acc[a][l] = x;
        }
    if (lane == 0) {
#pragma unroll
        for (int tt = 0; tt < 8; tt++)
#pragma unroll
            for (int l = 0; l < 8; l++)
                pbufW[((warp * 8 + tt) * 8 + l) * GRID + bid] = acc[tt][l];
#pragma unroll
        for (int l = 0; l < 8; l++)
            pbufW[(512 + warp * 8 + l) * GRID + bid] = acc[8][l];
    }
}

// ---------------------------------------------------------------------------
// K4: final W update (W_49 -> W_50) from P_49. 1 block x 576 threads.
//     Reads g_Wb[0] (written by launch 49), P from g_partialBuf[1].
// ---------------------------------------------------------------------------
__global__ __launch_bounds__(576) void k_iterWfin() {
    __shared__ float sVHt[512];
    __shared__ float sHHt[64];
    int tid = threadIdx.x;
    float s = 0.f;
    {
        const float4* p = (const float4*)&g_partialBuf[1][tid * GRID];
#pragma unroll 8
        for (int b = 0; b < GRID / 4; b++) { float4 v = p[b]; s += (v.x + v.y) + (v.z + v.w); }
    }
    if (tid < 512) sVHt[tid] = s; else sHHt[tid - 512] = s;
    __syncthreads();
    if (tid < 512) {
        int t = tid >> 3, l = tid & 7;
        float den = EPS_F;
#pragma unroll
        for (int j = 0; j < 8; j++) den += g_Wb[0][t * 8 + j] * sHHt[j * 8 + l];
        g_Wfin[tid] = g_Wb[0][tid] * sVHt[tid] / den;
    }
}

// ---------------------------------------------------------------------------
// K5: fused epilogue (R8-proven): A = w_post1@W (per-block redundant), then
//     vhat = W@h (error), y = relu(A@h), out = w_post2 @ y.  grid 256 x 256
// ---------------------------------------------------------------------------
__global__ __launch_bounds__(256) void k_final(const float* __restrict__ wp1,
                                               const float* __restrict__ wp2,
                                               float* __restrict__ out) {
    __shared__ __align__(16) float sW[512];
    __shared__ __align__(16) float sA[512];
    __shared__ __align__(16) float sP[4096];
    __shared__ float ssum[256];
    int tid = threadIdx.x;
    for (int i = tid; i < 512; i += 256) sW[i] = g_Wfin[i];
    for (int i = tid; i < 4096; i += 256) sP[i] = wp2[i];
    __syncthreads();

    {
        int t0 = tid >> 3, l0 = tid & 7;
        float s0 = 0.f;
#pragma unroll 8
        for (int c = 0; c < 64; c++) s0 += wp1[t0 * 64 + c] * sW[c * 8 + l0];
        sA[tid] = s0;
        int i1 = tid + 256;
        int t1 = i1 >> 3, l1 = i1 & 7;
        float s1 = 0.f;
#pragma unroll 8
        for (int c = 0; c < 64; c++) s1 += wp1[t1 * 64 + c] * sW[c * 8 + l1];
        sA[i1] = s1;
    }
    __syncthreads();

    int m = blockIdx.x * 256 + tid;
    float h[8];
#pragma unroll
    for (int l = 0; l < 8; l++) h[l] = g_H[l * MCOLS + m];

    float y[64];
    float err = 0.f;
#pragma unroll
    for (int t = 0; t < 64; t++) {
        const float4* w4 = (const float4*)&sW[t * 8];
        float4 wa = w4[0], wb = w4[1];
        float vh = wa.x * h[0] + wa.y * h[1] + wa.z * h[2] + wa.w * h[3]
                 + wb.x * h[4] + wb.y * h[5] + wb.z * h[6] + wb.w * h[7];
        const float4* a4 = (const float4*)&sA[t * 8];
        float4 aa = a4[0], ab = a4[1];
        float ya = aa.x * h[0] + aa.y * h[1] + aa.z * h[2] + aa.w * h[3]
                 + ab.x * h[4] + ab.y * h[5] + ab.z * h[6] + ab.w * h[7];
        float d = g_V[t * MCOLS + m] - vh;
        err += d * d;
        y[t] = fmaxf(ya, 0.f);
    }

#pragma unroll 1
    for (int t = 0; t < 64; t++) {
        const float4* p4 = (const float4*)&sP[t * 64];
        float o = 0.f;
#pragma unroll
        for (int q = 0; q < 16; q++) {
            float4 w = p4[q];
            o += w.x * y[4 * q] + w.y * y[4 * q + 1] + w.z * y[4 * q + 2] + w.w * y[4 * q + 3];
        }
        out[t * MCOLS + m] = o;
    }

    ssum[tid] = err; __syncthreads();
    for (int s = 128; s; s >>= 1) { if (tid < s) ssum[tid] += ssum[tid + s]; __syncthreads(); }
    if (tid == 0) g_red2[blockIdx.x] = ssum[0];
}

// ---------------------------------------------------------------------------
// K6: error
// ---------------------------------------------------------------------------
__global__ void k_err(float* __restrict__ out, int out_size) {
    __shared__ float s[256];
    int tid = threadIdx.x;
    s[tid] = g_red2[tid];
    __syncthreads();
    for (int st = 128; st; st >>= 1) { if (tid < st) s[tid] += s[tid + st]; __syncthreads(); }
    if (tid == 0) out[out_size - 1] = sqrtf(s[0]);
}

// ---------------------------------------------------------------------------
extern "C" void kernel_launch(void* const* d_in, const int* in_sizes, int n_in,
                              void* d_out, int out_size) {
    const float* eps  = (const float*)d_in[0];
    const float* wpre = (const float*)d_in[1];
    const float* bpre = (const float*)d_in[2];
    const float* wp1  = (const float*)d_in[3];
    const float* wp2  = (const float*)d_in[4];
    float* out = (float*)d_out;

    k_preconv<<<256, 256>>>(eps, wpre, bpre);
    k_init<<<2048, 256>>>();
    for (int it = 0; it < NMF_ITERS; it++)
        k_iter<<<GRID, 256>>>(it);
    k_iterWfin<<<1, 576>>>();
    k_final<<<256, 256>>>(wp1, wp2, out);
    k_err<<<1, 256>>>(out, out_size);
}

// round 10
// speedup vs baseline: 1.7170x; 1.1558x over previous
#include <cuda_runtime.h>
#include <math.h>
#include <stdint.h>

#define MCOLS 65536
#define TCH   64
#define LRANK 8
#define NMF_ITERS 50
#define EPS_F 1.1920929e-07f
#define GRID  128                 // blocks in k_iter; stride of partials
#define IBLK  512                 // threads per k_iter block

// ---------------------------------------------------------------------------
// Scratch (no allocations allowed)
// ---------------------------------------------------------------------------
__device__ __align__(16) float g_V[TCH * MCOLS];          // relu(conv), row-major
__device__ __align__(16) float g_H[LRANK * MCOLS];
__device__ __align__(16) float g_Wb[2][TCH * LRANK];      // W parity buffers
__device__ __align__(16) float g_Wfin[TCH * LRANK];       // W_50 for epilogue
__device__ __align__(16) float g_partialBuf[2][576 * GRID];  // [parity][idx][block]
__device__ float g_red[256];
__device__ float g_red2[256];

// PDL intrinsics guard
#if defined(__CUDA_ARCH__) && __CUDA_ARCH__ >= 900
#define GRID_DEP_SYNC() cudaGridDependencySynchronize()
#else
#define GRID_DEP_SYNC()
#endif

// ---------------------------------------------------------------------------
// Threefry-2x32 (JAX), 20 rounds
// ---------------------------------------------------------------------------
__device__ __forceinline__ void tf2x32(unsigned k0, unsigned k1,
                                       unsigned x0, unsigned x1,
                                       unsigned& o0, unsigned& o1) {
    unsigned ks2 = k0 ^ k1 ^ 0x1BD11BDAu;
    x0 += k0; x1 += k1;
#define TF_RND(r) { x0 += x1; x1 = (x1 << (r)) | (x1 >> (32 - (r))); x1 ^= x0; }
    TF_RND(13) TF_RND(15) TF_RND(26) TF_RND(6)
    x0 += k1;  x1 += ks2 + 1u;
    TF_RND(17) TF_RND(29) TF_RND(16) TF_RND(24)
    x0 += ks2; x1 += k0 + 2u;
    TF_RND(13) TF_RND(15) TF_RND(26) TF_RND(6)
    x0 += k0;  x1 += k1 + 3u;
    TF_RND(17) TF_RND(29) TF_RND(16) TF_RND(24)
    x0 += k1;  x1 += ks2 + 4u;
    TF_RND(13) TF_RND(15) TF_RND(26) TF_RND(6)
    x0 += ks2; x1 += k0 + 5u;
#undef TF_RND
    o0 = x0; o1 = x1;
}

__device__ __forceinline__ float bits_to_uniform(unsigned b) {
    return __uint_as_float((b >> 9) | 0x3f800000u) - 1.0f;
}

// ---------------------------------------------------------------------------
// K1: Vst = relu(w_pre @ eps + b_pre) + per-block sum   (proven)
// grid MUST be 256 x 256
// ---------------------------------------------------------------------------
__global__ __launch_bounds__(256) void k_preconv(const float* __restrict__ eps,
                                                 const float* __restrict__ wpre,
                                                 const float* __restrict__ bpre) {
    __shared__ __align__(16) float sT[4096];
    __shared__ float sb[64];
    __shared__ float ssum[256];
    int tid = threadIdx.x;
    for (int i = tid; i < 4096; i += 256) {
        int t = i >> 6, c = i & 63;
        sT[c * 64 + t] = wpre[i];
    }
    if (tid < 64) sb[tid] = bpre[tid];
    __syncthreads();

    int m = blockIdx.x * 256 + tid;
    float acc[64];
#pragma unroll
    for (int t = 0; t < 64; t++) acc[t] = sb[t];
#pragma unroll 1
    for (int c = 0; c < 64; c++) {
        float e = eps[c * MCOLS + m];
        const float4* wr = (const float4*)&sT[c * 64];
#pragma unroll
        for (int q = 0; q < 16; q++) {
            float4 w = wr[q];
            acc[4 * q + 0] += w.x * e;
            acc[4 * q + 1] += w.y * e;
            acc[4 * q + 2] += w.z * e;
            acc[4 * q + 3] += w.w * e;
        }
    }
    float ls = 0.f;
#pragma unroll
    for (int t = 0; t < 64; t++) {
        float v = fmaxf(acc[t], 0.f);
        g_V[t * MCOLS + m] = v;
        ls += v;
    }
    ssum[tid] = ls; __syncthreads();
    for (int s = 128; s; s >>= 1) { if (tid < s) ssum[tid] += ssum[tid + s]; __syncthreads(); }
    if (tid == 0) g_red[blockIdx.x] = ssum[0];
}

// ---------------------------------------------------------------------------
// K2: fused scalar+init (proven).  grid MUST be 2048 x 256. W0 -> g_Wb[0].
// ---------------------------------------------------------------------------
__global__ __launch_bounds__(256) void k_init() {
    GRID_DEP_SYNC();
    __shared__ float s[256];
    __shared__ unsigned skeys[4];
    __shared__ float savg;
    int tid = threadIdx.x;
    s[tid] = g_red[tid];
    __syncthreads();
    for (int st = 128; st; st >>= 1) { if (tid < st) s[tid] += s[tid + st]; __syncthreads(); }
    if (tid == 0) {
        float mean = s[0] / (float)(TCH * MCOLS);
        savg = sqrtf(mean / (float)LRANK);
        unsigned o0, o1;
        tf2x32(0u, 0u, 0u, 0u, o0, o1); skeys[0] = o0; skeys[1] = o1;  // kW
        tf2x32(0u, 0u, 0u, 1u, o0, o1); skeys[2] = o0; skeys[3] = o1;  // kH
    }
    __syncthreads();

    unsigned i = blockIdx.x * 256u + tid;   // < 524288
    float avg = savg;
    unsigned o0, o1;
    tf2x32(skeys[2], skeys[3], 0u, i, o0, o1);
    g_H[i] = avg * bits_to_uniform(o0 ^ o1);
    if (i < TCH * LRANK) {
        tf2x32(skeys[0], skeys[1], 0u, i, o0, o1);
        g_Wb[0][i] = avg * bits_to_uniform(o0 ^ o1);
    }
}

// ---------------------------------------------------------------------------
// K3: one fused NMF iteration. grid MUST be GRID=128 x IBLK=512 (1 col/thread).
//   prologue (k>0): every block redundantly reduces P_{k-1} (exact k_iterW
//     order per output) and computes W_k; block 0 publishes to g_Wb[(k+1)&1].
//   then: WtW, H update (H_k -> H_{k+1}), partials P_k -> g_partialBuf[k&1].
//   16 warps/SM: warp w owns V rows [4w, 4w+4); warps 0..7 also HHt row w.
// ---------------------------------------------------------------------------
__global__ __launch_bounds__(IBLK, 1) void k_iter(int it) {
    GRID_DEP_SYNC();
    __shared__ __align__(16) float sW[512];
    __shared__ __align__(16) float sWtW[64];
    __shared__ __align__(16) float sRed[576];
    __shared__ __align__(16) float sHn[8 * IBLK];
    int tid = threadIdx.x, lane = tid & 31, warp = tid >> 5;
    int bid = blockIdx.x;
    int m = bid * IBLK + tid;

    const float* __restrict__ Wold = g_Wb[it & 1];
    float* __restrict__ pbufW = g_partialBuf[it & 1];

    if (it > 0) {
        const float* __restrict__ P = g_partialBuf[(it + 1) & 1];  // P_{it-1}
        for (int o = tid; o < 576; o += IBLK) {
            const float4* p = (const float4*)&P[o * GRID];
            float s = 0.f;
#pragma unroll 8
            for (int b = 0; b < GRID / 4; b++) { float4 v = p[b]; s += (v.x + v.y) + (v.z + v.w); }
            sRed[o] = s;
        }
        __syncthreads();
        // W update, exact k_iterW math (1 entry/thread)
        {
            int t0 = tid >> 3, l0 = tid & 7;
            float den = EPS_F;
#pragma unroll
            for (int j = 0; j < 8; j++) den += Wold[t0 * 8 + j] * sRed[512 + j * 8 + l0];
            float nw = Wold[tid] * sRed[tid] / den;
            sW[tid < 512 ? tid : 0] = 0.f;   // (dead; tid<512 always true for write below)
            sW[tid] = nw;
            if (bid == 0) g_Wb[(it + 1) & 1][tid] = nw;
        }
    } else {
        sW[tid & 511] = Wold[tid & 511];
        if (bid == 0) g_Wb[1][tid & 511] = Wold[tid & 511];
    }
    __syncthreads();

    // WtW
    if (tid < 64) {
        int l = tid >> 3, j = tid & 7;
        float s = 0.f;
#pragma unroll 8
        for (int t = 0; t < 64; t++) s += sW[t * 8 + l] * sW[t * 8 + j];
        sWtW[tid] = s;
    }
    __syncthreads();

    // --- phase 1: wtv = W^T v_col ; H update (batched loads, MLP=16) ---
    float h[8], wtv[8];
#pragma unroll
    for (int l = 0; l < 8; l++) { h[l] = g_H[l * MCOLS + m]; wtv[l] = 0.f; }
#pragma unroll 1
    for (int tb = 0; tb < 64; tb += 16) {
        float v[16];
#pragma unroll
        for (int i = 0; i < 16; i++) v[i] = g_V[(tb + i) * MCOLS + m];
#pragma unroll
        for (int i = 0; i < 16; i++) {
            const float4* w4 = (const float4*)&sW[(tb + i) * 8];
            float4 wa = w4[0], wb = w4[1];
            wtv[0] += wa.x * v[i]; wtv[1] += wa.y * v[i];
            wtv[2] += wa.z * v[i]; wtv[3] += wa.w * v[i];
            wtv[4] += wb.x * v[i]; wtv[5] += wb.y * v[i];
            wtv[6] += wb.z * v[i]; wtv[7] += wb.w * v[i];
        }
    }
#pragma unroll
    for (int l = 0; l < 8; l++) {
        const float4* q4 = (const float4*)&sWtW[l * 8];
        float4 qa = q4[0], qb = q4[1];
        float den = EPS_F
            + qa.x * h[0] + qa.y * h[1] + qa.z * h[2] + qa.w * h[3]
            + qb.x * h[4] + qb.y * h[5] + qb.z * h[6] + qb.w * h[7];
        float hn = h[l] * wtv[l] / den;
        g_H[l * MCOLS + m] = hn;
        sHn[l * IBLK + tid] = hn;
    }
    __syncthreads();

    // --- phase 2: warp w: VHt rows [4w,4w+4); warps 0..7 also HHt row w ---
    float acc[4][8], acch[8];
#pragma unroll
    for (int a = 0; a < 4; a++)
#pragma unroll
        for (int l = 0; l < 8; l++) acc[a][l] = 0.f;
#pragma unroll
    for (int l = 0; l < 8; l++) acch[l] = 0.f;

#pragma unroll 2
    for (int gg = 0; gg < 16; gg++) {
        int mm = gg * 32 + lane;
        float hl[8];
#pragma unroll
        for (int l = 0; l < 8; l++) hl[l] = sHn[l * IBLK + mm];
        float v0 = g_V[(warp * 4 + 0) * MCOLS + bid * IBLK + mm];
        float v1 = g_V[(warp * 4 + 1) * MCOLS + bid * IBLK + mm];
        float v2 = g_V[(warp * 4 + 2) * MCOLS + bid * IBLK + mm];
        float v3 = g_V[(warp * 4 + 3) * MCOLS + bid * IBLK + mm];
#pragma unroll
        for (int l = 0; l < 8; l++) {
            acc[0][l] += v0 * hl[l];
            acc[1][l] += v1 * hl[l];
            acc[2][l] += v2 * hl[l];
            acc[3][l] += v3 * hl[l];
        }
        if (warp < 8) {
            float hw = hl[warp];
#pragma unroll
            for (int l = 0; l < 8; l++) acch[l] += hw * hl[l];
        }
    }

#pragma unroll
    for (int a = 0; a < 4; a++)
#pragma unroll
        for (int l = 0; l < 8; l++) {
            float x = acc[a][l];
#pragma unroll
            for (int s = 16; s; s >>= 1) x += __shfl_xor_sync(0xffffffffu, x, s);
            acc[a][l] = x;
        }
#pragma unroll
    for (int l = 0; l < 8; l++) {
        float x = acch[l];
#pragma unroll
        for (int s = 16; s; s >>= 1) x += __shfl_xor_sync(0xffffffffu, x, s);
        acch[l] = x;
    }
    if (lane == 0) {
#pragma unroll
        for (int tt = 0; tt < 4; tt++)
#pragma unroll
            for (int l = 0; l < 8; l++)
                pbufW[((warp * 4 + tt) * 8 + l) * GRID + bid] = acc[tt][l];
        if (warp < 8) {
#pragma unroll
            for (int l = 0; l < 8; l++)
                pbufW[(512 + warp * 8 + l) * GRID + bid] = acch[l];
        }
    }
}

// ---------------------------------------------------------------------------
// K4: final W update (W_49 -> W_50) from P_49. 1 block x 576 threads.
// ---------------------------------------------------------------------------
__global__ __launch_bounds__(576) void k_iterWfin() {
    GRID_DEP_SYNC();
    __shared__ float sVHt[512];
    __shared__ float sHHt[64];
    int tid = threadIdx.x;
    float s = 0.f;
    {
        const float4* p = (const float4*)&g_partialBuf[1][tid * GRID];
#pragma unroll 8
        for (int b = 0; b < GRID / 4; b++) { float4 v = p[b]; s += (v.x + v.y) + (v.z + v.w); }
    }
    if (tid < 512) sVHt[tid] = s; else sHHt[tid - 512] = s;
    __syncthreads();
    if (tid < 512) {
        int t = tid >> 3, l = tid & 7;
        float den = EPS_F;
#pragma unroll
        for (int j = 0; j < 8; j++) den += g_Wb[0][t * 8 + j] * sHHt[j * 8 + l];
        g_Wfin[tid] = g_Wb[0][tid] * sVHt[tid] / den;
    }
}

// ---------------------------------------------------------------------------
// K5: fused epilogue (proven): A = w_post1@W (per-block redundant), then
//     vhat = W@h (error), y = relu(A@h), out = w_post2 @ y.  grid 256 x 256
// ---------------------------------------------------------------------------
__global__ __launch_bounds__(256) void k_final(const float* __restrict__ wp1,
                                               const float* __restrict__ wp2,
                                               float* __restrict__ out) {
    GRID_DEP_SYNC();
    __shared__ __align__(16) float sW[512];
    __shared__ __align__(16) float sA[512];
    __shared__ __align__(16) float sP[4096];
    __shared__ float ssum[256];
    int tid = threadIdx.x;
    for (int i = tid; i < 512; i += 256) sW[i] = g_Wfin[i];
    for (int i = tid; i < 4096; i += 256) sP[i] = wp2[i];
    __syncthreads();

    {
        int t0 = tid >> 3, l0 = tid & 7;
        float s0 = 0.f;
#pragma unroll 8
        for (int c = 0; c < 64; c++) s0 += wp1[t0 * 64 + c] * sW[c * 8 + l0];
        sA[tid] = s0;
        int i1 = tid + 256;
        int t1 = i1 >> 3, l1 = i1 & 7;
        float s1 = 0.f;
#pragma unroll 8
        for (int c = 0; c < 64; c++) s1 += wp1[t1 * 64 + c] * sW[c * 8 + l1];
        sA[i1] = s1;
    }
    __syncthreads();

    int m = blockIdx.x * 256 + tid;
    float h[8];
#pragma unroll
    for (int l = 0; l < 8; l++) h[l] = g_H[l * MCOLS + m];

    float y[64];
    float err = 0.f;
#pragma unroll
    for (int t = 0; t < 64; t++) {
        const float4* w4 = (const float4*)&sW[t * 8];
        float4 wa = w4[0], wb = w4[1];
        float vh = wa.x * h[0] + wa.y * h[1] + wa.z * h[2] + wa.w * h[3]
                 + wb.x * h[4] + wb.y * h[5] + wb.z * h[6] + wb.w * h[7];
        const float4* a4 = (const float4*)&sA[t * 8];
        float4 aa = a4[0], ab = a4[1];
        float ya = aa.x * h[0] + aa.y * h[1] + aa.z * h[2] + aa.w * h[3]
                 + ab.x * h[4] + ab.y * h[5] + ab.z * h[6] + ab.w * h[7];
        float d = g_V[t * MCOLS + m] - vh;
        err += d * d;
        y[t] = fmaxf(ya, 0.f);
    }

#pragma unroll 1
    for (int t = 0; t < 64; t++) {
        const float4* p4 = (const float4*)&sP[t * 64];
        float o = 0.f;
#pragma unroll
        for (int q = 0; q < 16; q++) {
            float4 w = p4[q];
            o += w.x * y[4 * q] + w.y * y[4 * q + 1] + w.z * y[4 * q + 2] + w.w * y[4 * q + 3];
        }
        out[t * MCOLS + m] = o;
    }

    ssum[tid] = err; __syncthreads();
    for (int s = 128; s; s >>= 1) { if (tid < s) ssum[tid] += ssum[tid + s]; __syncthreads(); }
    if (tid == 0) g_red2[blockIdx.x] = ssum[0];
}

// ---------------------------------------------------------------------------
// K6: error
// ---------------------------------------------------------------------------
__global__ void k_err(float* __restrict__ out, int out_size) {
    GRID_DEP_SYNC();
    __shared__ float s[256];
    int tid = threadIdx.x;
    s[tid] = g_red2[tid];
    __syncthreads();
    for (int st = 128; st; st >>= 1) { if (tid < st) s[tid] += s[tid + st]; __syncthreads(); }
    if (tid == 0) out[out_size - 1] = sqrtf(s[0]);
}

// ---------------------------------------------------------------------------
// Host: all launches via cudaLaunchKernelEx with PDL attribute so successor
// launch setup overlaps predecessor execution (graph-capturable).
// ---------------------------------------------------------------------------
template <typename F, typename... Args>
static void launch_pdl(dim3 grid, dim3 block, F func, Args... args) {
    cudaLaunchConfig_t cfg = {};
    cfg.gridDim = grid;
    cfg.blockDim = block;
    cudaLaunchAttribute attr[1];
    attr[0].id = cudaLaunchAttributeProgrammaticStreamSerialization;
    attr[0].val.programmaticStreamSerializationAllowed = 1;
    cfg.attrs = attr;
    cfg.numAttrs = 1;
    cudaLaunchKernelEx(&cfg, func, args...);
}

extern "C" void kernel_launch(void* const* d_in, const int* in_sizes, int n_in,
                              void* d_out, int out_size) {
    const float* eps  = (const float*)d_in[0];
    const float* wpre = (const float*)d_in[1];
    const float* bpre = (const float*)d_in[2];
    const float* wp1  = (const float*)d_in[3];
    const float* wp2  = (const float*)d_in[4];
    float* out = (float*)d_out;

    launch_pdl(dim3(256), dim3(256), k_preconv, eps, wpre, bpre);
    launch_pdl(dim3(2048), dim3(256), k_init);
    for (int it = 0; it < NMF_ITERS; it++)
        launch_pdl(dim3(GRID), dim3(IBLK), k_iter, it);
    launch_pdl(dim3(1), dim3(576), k_iterWfin);
    launch_pdl(dim3(256), dim3(256), k_final, wp1, wp2, out);
    launch_pdl(dim3(1), dim3(256), k_err, out, out_size);
}

// round 11
// speedup vs baseline: 1.9615x; 1.1424x over previous
#include <cuda_runtime.h>
#include <math.h>
#include <stdint.h>

#define MCOLS 65536
#define TCH   64
#define LRANK 8
#define NMF_ITERS 50
#define EPS_F 1.1920929e-07f
#define GRID  128                 // blocks in k_iter; stride of partials
#define IBLK  512                 // threads per k_iter block

typedef unsigned long long ull;

// ---------------------------------------------------------------------------
// Scratch (no allocations allowed)
// ---------------------------------------------------------------------------
__device__ __align__(16) float g_V[TCH * MCOLS];          // relu(conv), row-major
__device__ __align__(16) float g_H[LRANK * MCOLS];
__device__ __align__(16) float g_Wb[2][TCH * LRANK];      // W parity buffers
__device__ __align__(16) float g_Wfin[TCH * LRANK];       // W_50 for epilogue
__device__ __align__(16) float g_partialBuf[2][576 * GRID];  // [parity][idx][block]
__device__ float g_red[256];
__device__ float g_red2[256];

// PDL intrinsics guard
#if defined(__CUDA_ARCH__) && __CUDA_ARCH__ >= 900
#define GRID_DEP_SYNC() cudaGridDependencySynchronize()
#else
#define GRID_DEP_SYNC()
#endif

// ---------------------------------------------------------------------------
// Packed fp32x2 helpers (sm_103a FFMA2 path; per-lane results bitwise
// identical to scalar FFMA)
// ---------------------------------------------------------------------------
__device__ __forceinline__ ull pack2(float lo, float hi) {
    ull r;
    asm("mov.b64 %0, {%1, %2};" : "=l"(r)
        : "r"(__float_as_uint(lo)), "r"(__float_as_uint(hi)));
    return r;
}
__device__ __forceinline__ void unpack2(ull v, float& lo, float& hi) {
    unsigned a, b;
    asm("mov.b64 {%0, %1}, %2;" : "=r"(a), "=r"(b) : "l"(v));
    lo = __uint_as_float(a); hi = __uint_as_float(b);
}
__device__ __forceinline__ ull fma2(ull a, ull b, ull c) {
    ull d;
    asm("fma.rn.f32x2 %0, %1, %2, %3;" : "=l"(d) : "l"(a), "l"(b), "l"(c));
    return d;
}

// ---------------------------------------------------------------------------
// Threefry-2x32 (JAX), 20 rounds
// ---------------------------------------------------------------------------
__device__ __forceinline__ void tf2x32(unsigned k0, unsigned k1,
                                       unsigned x0, unsigned x1,
                                       unsigned& o0, unsigned& o1) {
    unsigned ks2 = k0 ^ k1 ^ 0x1BD11BDAu;
    x0 += k0; x1 += k1;
#define TF_RND(r) { x0 += x1; x1 = (x1 << (r)) | (x1 >> (32 - (r))); x1 ^= x0; }
    TF_RND(13) TF_RND(15) TF_RND(26) TF_RND(6)
    x0 += k1;  x1 += ks2 + 1u;
    TF_RND(17) TF_RND(29) TF_RND(16) TF_RND(24)
    x0 += ks2; x1 += k0 + 2u;
    TF_RND(13) TF_RND(15) TF_RND(26) TF_RND(6)
    x0 += k0;  x1 += k1 + 3u;
    TF_RND(17) TF_RND(29) TF_RND(16) TF_RND(24)
    x0 += k1;  x1 += ks2 + 4u;
    TF_RND(13) TF_RND(15) TF_RND(26) TF_RND(6)
    x0 += ks2; x1 += k0 + 5u;
#undef TF_RND
    o0 = x0; o1 = x1;
}

__device__ __forceinline__ float bits_to_uniform(unsigned b) {
    return __uint_as_float((b >> 9) | 0x3f800000u) - 1.0f;
}

// ---------------------------------------------------------------------------
// K1: Vst = relu(w_pre @ eps + b_pre) + per-block sum   (proven)
// grid MUST be 256 x 256
// ---------------------------------------------------------------------------
__global__ __launch_bounds__(256) void k_preconv(const float* __restrict__ eps,
                                                 const float* __restrict__ wpre,
                                                 const float* __restrict__ bpre) {
    __shared__ __align__(16) float sT[4096];
    __shared__ float sb[64];
    __shared__ float ssum[256];
    int tid = threadIdx.x;
    for (int i = tid; i < 4096; i += 256) {
        int t = i >> 6, c = i & 63;
        sT[c * 64 + t] = wpre[i];
    }
    if (tid < 64) sb[tid] = bpre[tid];
    __syncthreads();

    int m = blockIdx.x * 256 + tid;
    float acc[64];
#pragma unroll
    for (int t = 0; t < 64; t++) acc[t] = sb[t];
#pragma unroll 1
    for (int c = 0; c < 64; c++) {
        float e = eps[c * MCOLS + m];
        const float4* wr = (const float4*)&sT[c * 64];
#pragma unroll
        for (int q = 0; q < 16; q++) {
            float4 w = wr[q];
            acc[4 * q + 0] += w.x * e;
            acc[4 * q + 1] += w.y * e;
            acc[4 * q + 2] += w.z * e;
            acc[4 * q + 3] += w.w * e;
        }
    }
    float ls = 0.f;
#pragma unroll
    for (int t = 0; t < 64; t++) {
        float v = fmaxf(acc[t], 0.f);
        g_V[t * MCOLS + m] = v;
        ls += v;
    }
    ssum[tid] = ls; __syncthreads();
    for (int s = 128; s; s >>= 1) { if (tid < s) ssum[tid] += ssum[tid + s]; __syncthreads(); }
    if (tid == 0) g_red[blockIdx.x] = ssum[0];
}

// ---------------------------------------------------------------------------
// K2: fused scalar+init (proven).  grid MUST be 2048 x 256. W0 -> g_Wb[0].
// ---------------------------------------------------------------------------
__global__ __launch_bounds__(256) void k_init() {
    GRID_DEP_SYNC();
    __shared__ float s[256];
    __shared__ unsigned skeys[4];
    __shared__ float savg;
    int tid = threadIdx.x;
    s[tid] = g_red[tid];
    __syncthreads();
    for (int st = 128; st; st >>= 1) { if (tid < st) s[tid] += s[tid + st]; __syncthreads(); }
    if (tid == 0) {
        float mean = s[0] / (float)(TCH * MCOLS);
        savg = sqrtf(mean / (float)LRANK);
        unsigned o0, o1;
        tf2x32(0u, 0u, 0u, 0u, o0, o1); skeys[0] = o0; skeys[1] = o1;  // kW
        tf2x32(0u, 0u, 0u, 1u, o0, o1); skeys[2] = o0; skeys[3] = o1;  // kH
    }
    __syncthreads();

    unsigned i = blockIdx.x * 256u + tid;   // < 524288
    float avg = savg;
    unsigned o0, o1;
    tf2x32(skeys[2], skeys[3], 0u, i, o0, o1);
    g_H[i] = avg * bits_to_uniform(o0 ^ o1);
    if (i < TCH * LRANK) {
        tf2x32(skeys[0], skeys[1], 0u, i, o0, o1);
        g_Wb[0][i] = avg * bits_to_uniform(o0 ^ o1);
    }
}

// ---------------------------------------------------------------------------
// K3: one fused NMF iteration. grid MUST be GRID=128 x IBLK=512 (1 col/thread).
//   prologue (k>0): every block redundantly reduces P_{k-1} (exact k_iterW
//     order per output) and computes W_k; block 0 publishes to g_Wb[(k+1)&1].
//   then: distributed WtW, packed-f32x2 H update, packed-f32x2 partials.
// ---------------------------------------------------------------------------
__global__ __launch_bounds__(IBLK, 1) void k_iter(int it) {
    GRID_DEP_SYNC();
    __shared__ __align__(16) float sW[512];
    __shared__ __align__(16) float sWtW[64];
    __shared__ __align__(16) float sWtWp[512];    // [lj][oct] partials
    __shared__ __align__(16) float sRed[576];
    __shared__ __align__(16) ull  sHnP[4 * IBLK]; // packed (h2p, h2p+1) per col
    int tid = threadIdx.x, lane = tid & 31, warp = tid >> 5;
    int bid = blockIdx.x;
    int m = bid * IBLK + tid;

    const float* __restrict__ Wold = g_Wb[it & 1];
    float* __restrict__ pbufW = g_partialBuf[it & 1];

    // hoist: H loads are independent of W/partials — in flight under prologue
    float h[8];
#pragma unroll
    for (int l = 0; l < 8; l++) h[l] = g_H[l * MCOLS + m];

    if (it > 0) {
        const float* __restrict__ P = g_partialBuf[(it + 1) & 1];  // P_{it-1}
        for (int o = tid; o < 576; o += IBLK) {
            const float4* p = (const float4*)&P[o * GRID];
            float s = 0.f;
#pragma unroll 8
            for (int b = 0; b < GRID / 4; b++) { float4 v = p[b]; s += (v.x + v.y) + (v.z + v.w); }
            sRed[o] = s;
        }
        __syncthreads();
        // W update, exact k_iterW math (1 entry/thread)
        {
            int t0 = tid >> 3, l0 = tid & 7;
            float den = EPS_F;
#pragma unroll
            for (int j = 0; j < 8; j++) den += Wold[t0 * 8 + j] * sRed[512 + j * 8 + l0];
            float nw = Wold[tid] * sRed[tid] / den;
            sW[tid] = nw;
            if (bid == 0) g_Wb[(it + 1) & 1][tid] = nw;
        }
    } else {
        sW[tid] = Wold[tid];
        if (bid == 0) g_Wb[1][tid] = Wold[tid];
    }
    __syncthreads();

    // --- distributed WtW partials (8-term dot per thread) + phase-1 V loop ---
    {
        int lj = tid & 63, oct = tid >> 6;            // oct in [0,8)
        int l = lj >> 3, j = lj & 7;
        float s = 0.f;
#pragma unroll
        for (int tt = 0; tt < 8; tt++) {
            int t = oct * 8 + tt;
            s += sW[t * 8 + l] * sW[t * 8 + j];
        }
        sWtWp[lj * 8 + oct] = s;
    }

    // phase 1: wtv = W^T v_col, packed pairs (bitwise == scalar order)
    ull wtvP[4] = {0ull, 0ull, 0ull, 0ull};
    const ull* sW2 = (const ull*)sW;                  // pairs (l, l+1) per t
#pragma unroll 1
    for (int tb = 0; tb < 64; tb += 16) {
        float v[16];
#pragma unroll
        for (int i = 0; i < 16; i++) v[i] = g_V[(tb + i) * MCOLS + m];
#pragma unroll
        for (int i = 0; i < 16; i++) {
            ull vp = pack2(v[i], v[i]);
            int t = tb + i;
            wtvP[0] = fma2(sW2[t * 4 + 0], vp, wtvP[0]);
            wtvP[1] = fma2(sW2[t * 4 + 1], vp, wtvP[1]);
            wtvP[2] = fma2(sW2[t * 4 + 2], vp, wtvP[2]);
            wtvP[3] = fma2(sW2[t * 4 + 3], vp, wtvP[3]);
        }
    }
    float wtv[8];
#pragma unroll
    for (int p = 0; p < 4; p++) unpack2(wtvP[p], wtv[2 * p], wtv[2 * p + 1]);
    __syncthreads();

    // finalize WtW (64 threads, sequential octant sum)
    if (tid < 64) {
        float s = 0.f;
#pragma unroll
        for (int o = 0; o < 8; o++) s += sWtWp[tid * 8 + o];
        sWtW[tid] = s;
    }
    __syncthreads();

    // H update (scalar den, exact R10 order)
    float hn[8];
#pragma unroll
    for (int l = 0; l < 8; l++) {
        const float4* q4 = (const float4*)&sWtW[l * 8];
        float4 qa = q4[0], qb = q4[1];
        float den = EPS_F
            + qa.x * h[0] + qa.y * h[1] + qa.z * h[2] + qa.w * h[3]
            + qb.x * h[4] + qb.y * h[5] + qb.z * h[6] + qb.w * h[7];
        hn[l] = h[l] * wtv[l] / den;
        g_H[l * MCOLS + m] = hn[l];
    }
#pragma unroll
    for (int p = 0; p < 4; p++) sHnP[p * IBLK + tid] = pack2(hn[2 * p], hn[2 * p + 1]);
    __syncthreads();

    // --- phase 2: packed partial VHt (warp: rows 4w..4w+3) + HHt (warps 0-7) ---
    ull accP[4][4], acchP[4];
#pragma unroll
    for (int a = 0; a < 4; a++)
#pragma unroll
        for (int p = 0; p < 4; p++) accP[a][p] = 0ull;
#pragma unroll
    for (int p = 0; p < 4; p++) acchP[p] = 0ull;

    const float* sHnF = (const float*)sHnP;
#pragma unroll 2
    for (int gg = 0; gg < 16; gg++) {
        int mm = gg * 32 + lane;
        ull hlP0 = sHnP[0 * IBLK + mm];
        ull hlP1 = sHnP[1 * IBLK + mm];
        ull hlP2 = sHnP[2 * IBLK + mm];
        ull hlP3 = sHnP[3 * IBLK + mm];
        float v0 = g_V[(warp * 4 + 0) * MCOLS + bid * IBLK + mm];
        float v1 = g_V[(warp * 4 + 1) * MCOLS + bid * IBLK + mm];
        float v2 = g_V[(warp * 4 + 2) * MCOLS + bid * IBLK + mm];
        float v3 = g_V[(warp * 4 + 3) * MCOLS + bid * IBLK + mm];
        ull vp0 = pack2(v0, v0), vp1 = pack2(v1, v1);
        ull vp2 = pack2(v2, v2), vp3 = pack2(v3, v3);
        accP[0][0] = fma2(vp0, hlP0, accP[0][0]);
        accP[0][1] = fma2(vp0, hlP1, accP[0][1]);
        accP[0][2] = fma2(vp0, hlP2, accP[0][2]);
        accP[0][3] = fma2(vp0, hlP3, accP[0][3]);
        accP[1][0] = fma2(vp1, hlP0, accP[1][0]);
        accP[1][1] = fma2(vp1, hlP1, accP[1][1]);
        accP[1][2] = fma2(vp1, hlP2, accP[1][2]);
        accP[1][3] = fma2(vp1, hlP3, accP[1][3]);
        accP[2][0] = fma2(vp2, hlP0, accP[2][0]);
        accP[2][1] = fma2(vp2, hlP1, accP[2][1]);
        accP[2][2] = fma2(vp2, hlP2, accP[2][2]);
        accP[2][3] = fma2(vp2, hlP3, accP[2][3]);
        accP[3][0] = fma2(vp3, hlP0, accP[3][0]);
        accP[3][1] = fma2(vp3, hlP1, accP[3][1]);
        accP[3][2] = fma2(vp3, hlP2, accP[3][2]);
        accP[3][3] = fma2(vp3, hlP3, accP[3][3]);
        if (warp < 8) {
            float hw = sHnF[((warp >> 1) * IBLK + mm) * 2 + (warp & 1)];
            ull hwp = pack2(hw, hw);
            acchP[0] = fma2(hwp, hlP0, acchP[0]);
            acchP[1] = fma2(hwp, hlP1, acchP[1]);
            acchP[2] = fma2(hwp, hlP2, acchP[2]);
            acchP[3] = fma2(hwp, hlP3, acchP[3]);
        }
    }

    // unpack to scalars (same values as R10), butterfly, store partials
    float acc[4][8], acch[8];
#pragma unroll
    for (int a = 0; a < 4; a++)
#pragma unroll
        for (int p = 0; p < 4; p++) unpack2(accP[a][p], acc[a][2 * p], acc[a][2 * p + 1]);
#pragma unroll
    for (int p = 0; p < 4; p++) unpack2(acchP[p], acch[2 * p], acch[2 * p + 1]);

#pragma unroll
    for (int a = 0; a < 4; a++)
#pragma unroll
        for (int l = 0; l < 8; l++) {
            float x = acc[a][l];
#pragma unroll
            for (int s = 16; s; s >>= 1) x += __shfl_xor_sync(0xffffffffu, x, s);
            acc[a][l] = x;
        }
#pragma unroll
    for (int l = 0; l < 8; l++) {
        float x = acch[l];
#pragma unroll
        for (int s = 16; s; s >>= 1) x += __shfl_xor_sync(0xffffffffu, x, s);
        acch[l] = x;
    }
    if (lane == 0) {
#pragma unroll
        for (int tt = 0; tt < 4; tt++)
#pragma unroll
            for (int l = 0; l < 8; l++)
                pbufW[((warp * 4 + tt) * 8 + l) * GRID + bid] = acc[tt][l];
        if (warp < 8) {
#pragma unroll
            for (int l = 0; l < 8; l++)
                pbufW[(512 + warp * 8 + l) * GRID + bid] = acch[l];
        }
    }
}

// ---------------------------------------------------------------------------
// K4: final W update (W_49 -> W_50) from P_49. 1 block x 576 threads.
// ---------------------------------------------------------------------------
__global__ __launch_bounds__(576) void k_iterWfin() {
    GRID_DEP_SYNC();
    __shared__ float sVHt[512];
    __shared__ float sHHt[64];
    int tid = threadIdx.x;
    float s = 0.f;
    {
        const float4* p = (const float4*)&g_partialBuf[1][tid * GRID];
#pragma unroll 8
        for (int b = 0; b < GRID / 4; b++) { float4 v = p[b]; s += (v.x + v.y) + (v.z + v.w); }
    }
    if (tid < 512) sVHt[tid] = s; else sHHt[tid - 512] = s;
    __syncthreads();
    if (tid < 512) {
        int t = tid >> 3, l = tid & 7;
        float den = EPS_F;
#pragma unroll
        for (int j = 0; j < 8; j++) den += g_Wb[0][t * 8 + j] * sHHt[j * 8 + l];
        g_Wfin[tid] = g_Wb[0][tid] * sVHt[tid] / den;
    }
}

// ---------------------------------------------------------------------------
// K5: fused epilogue (proven): A = w_post1@W (per-block redundant), then
//     vhat = W@h (error), y = relu(A@h), out = w_post2 @ y.  grid 256 x 256
// ---------------------------------------------------------------------------
__global__ __launch_bounds__(256) void k_final(const float* __restrict__ wp1,
                                               const float* __restrict__ wp2,
                                               float* __restrict__ out) {
    GRID_DEP_SYNC();
    __shared__ __align__(16) float sW[512];
    __shared__ __align__(16) float sA[512];
    __shared__ __align__(16) float sP[4096];
    __shared__ float ssum[256];
    int tid = threadIdx.x;
    for (int i = tid; i < 512; i += 256) sW[i] = g_Wfin[i];
    for (int i = tid; i < 4096; i += 256) sP[i] = wp2[i];
    __syncthreads();

    {
        int t0 = tid >> 3, l0 = tid & 7;
        float s0 = 0.f;
#pragma unroll 8
        for (int c = 0; c < 64; c++) s0 += wp1[t0 * 64 + c] * sW[c * 8 + l0];
        sA[tid] = s0;
        int i1 = tid + 256;
        int t1 = i1 >> 3, l1 = i1 & 7;
        float s1 = 0.f;
#pragma unroll 8
        for (int c = 0; c < 64; c++) s1 += wp1[t1 * 64 + c] * sW[c * 8 + l1];
        sA[i1] = s1;
    }
    __syncthreads();

    int m = blockIdx.x * 256 + tid;
    float h[8];
#pragma unroll
    for (int l = 0; l < 8; l++) h[l] = g_H[l * MCOLS + m];

    float y[64];
    float err = 0.f;
#pragma unroll
    for (int t = 0; t < 64; t++) {
        const float4* w4 = (const float4*)&sW[t * 8];
        float4 wa = w4[0], wb = w4[1];
        float vh = wa.x * h[0] + wa.y * h[1] + wa.z * h[2] + wa.w * h[3]
                 + wb.x * h[4] + wb.y * h[5] + wb.z * h[6] + wb.w * h[7];
        const float4* a4 = (const float4*)&sA[t * 8];
        float4 aa = a4[0], ab = a4[1];
        float ya = aa.x * h[0] + aa.y * h[1] + aa.z * h[2] + aa.w * h[3]
                 + ab.x * h[4] + ab.y * h[5] + ab.z * h[6] + ab.w * h[7];
        float d = g_V[t * MCOLS + m] - vh;
        err += d * d;
        y[t] = fmaxf(ya, 0.f);
    }

#pragma unroll 1
    for (int t = 0; t < 64; t++) {
        const float4* p4 = (const float4*)&sP[t * 64];
        float o = 0.f;
#pragma unroll
        for (int q = 0; q < 16; q++) {
            float4 w = p4[q];
            o += w.x * y[4 * q] + w.y * y[4 * q + 1] + w.z * y[4 * q + 2] + w.w * y[4 * q + 3];
        }
        out[t * MCOLS + m] = o;
    }

    ssum[tid] = err; __syncthreads();
    for (int s = 128; s; s >>= 1) { if (tid < s) ssum[tid] += ssum[tid + s]; __syncthreads(); }
    if (tid == 0) g_red2[blockIdx.x] = ssum[0];
}

// ---------------------------------------------------------------------------
// K6: error
// ---------------------------------------------------------------------------
__global__ void k_err(float* __restrict__ out, int out_size) {
    GRID_DEP_SYNC();
    __shared__ float s[256];
    int tid = threadIdx.x;
    s[tid] = g_red2[tid];
    __syncthreads();
    for (int st = 128; st; st >>= 1) { if (tid < st) s[tid] += s[tid + st]; __syncthreads(); }
    if (tid == 0) out[out_size - 1] = sqrtf(s[0]);
}

// ---------------------------------------------------------------------------
// Host: PDL launches (graph-capturable)
// ---------------------------------------------------------------------------
template <typename F, typename... Args>
static void launch_pdl(dim3 grid, dim3 block, F func, Args... args) {
    cudaLaunchConfig_t cfg = {};
    cfg.gridDim = grid;
    cfg.blockDim = block;
    cudaLaunchAttribute attr[1];
    attr[0].id = cudaLaunchAttributeProgrammaticStreamSerialization;
    attr[0].val.programmaticStreamSerializationAllowed = 1;
    cfg.attrs = attr;
    cfg.numAttrs = 1;
    cudaLaunchKernelEx(&cfg, func, args...);
}

extern "C" void kernel_launch(void* const* d_in, const int* in_sizes, int n_in,
                              void* d_out, int out_size) {
    const float* eps  = (const float*)d_in[0];
    const float* wpre = (const float*)d_in[1];
    const float* bpre = (const float*)d_in[2];
    const float* wp1  = (const float*)d_in[3];
    const float* wp2  = (const float*)d_in[4];
    float* out = (float*)d_out;

    launch_pdl(dim3(256), dim3(256), k_preconv, eps, wpre, bpre);
    launch_pdl(dim3(2048), dim3(256), k_init);
    for (int it = 0; it < NMF_ITERS; it++)
        launch_pdl(dim3(GRID), dim3(IBLK), k_iter, it);
    launch_pdl(dim3(1), dim3(576), k_iterWfin);
    launch_pdl(dim3(256), dim3(256), k_final, wp1, wp2, out);
    launch_pdl(dim3(1), dim3(256), k_err, out, out_size);
}